// round 5
// baseline (speedup 1.0000x reference)
#include <cuda_runtime.h>

#define BB 16384
#define KK 4096
#define CHUNKS 128          // row-chunks for pass1
#define RPB (BB / CHUNKS)   // 128 rows per chunk
#define CPB 1024            // columns per pass1 block (256 thr * float4)
#define NTHR 256            // pass1 / fixup block size
#define WTHR 512            // wide row-kernel block size (16 warps)
#define FROWS 32            // rows per fused block
#define FBLK (BB / FROWS)   // 512 fused blocks
#define OROWS 16            // rows per final block
#define GRP 16              // reduction groups for two-stage fixups
#define INV_EPS 20.0f       // 1/0.05

// ---- scratch (device globals; no allocation) ----
__device__ float    g_part_m[CHUNKS][KK];
__device__ float    g_part_s[CHUNKS][KK];
__device__ float    g_partp[FBLK][KK];   // fused col partials (8.4 MB)
__device__ float    g_p2[GRP][KK];       // stage-A partials
__device__ float    g_a[KK];             // a[k]
__device__ unsigned g_Mbits;             // order-encoded global max (0-init at load;
                                         // atomicMax idempotent across graph replays)

__device__ __forceinline__ unsigned enc_f(float x) {
    unsigned u = __float_as_uint(x);
    return (u & 0x80000000u) ? ~u : (u | 0x80000000u);
}
__device__ __forceinline__ float dec_f(unsigned u) {
    return (u & 0x80000000u) ? __uint_as_float(u & 0x7FFFFFFFu)
                             : __uint_as_float(~u);
}

// Single-barrier 16-warp row-sum, double-buffered by parity. Deterministic:
// fixed shuffle tree + fixed 16-slot fold, identical in every thread.
__device__ __forceinline__ float rowReduce16(float v, float (*slot)[16], int par) {
    #pragma unroll
    for (int o = 16; o; o >>= 1) v += __shfl_xor_sync(0xffffffffu, v, o);
    if ((threadIdx.x & 31) == 0) slot[par][threadIdx.x >> 5] = v;
    __syncthreads();
    int lane = threadIdx.x & 31;
    float s = (lane < 16) ? slot[par][lane] : 0.f;
    s += __shfl_xor_sync(0xffffffffu, s, 8);
    s += __shfl_xor_sync(0xffffffffu, s, 4);
    s += __shfl_xor_sync(0xffffffffu, s, 2);
    s += __shfl_xor_sync(0xffffffffu, s, 1);
    return __shfl_sync(0xffffffffu, s, 0);
}

// Pass 1: per-chunk online column (over b) sums of exp with local max,
// plus global max via atomicMax.
__global__ __launch_bounds__(NTHR) void k_pass1(const float* __restrict__ x) {
    const int    k0   = blockIdx.x * CPB + threadIdx.x * 4;
    const size_t base = (size_t)blockIdx.y * RPB * KK + k0;
    const float  NEGINF = __int_as_float(0xff800000);
    float m0 = NEGINF, m1 = NEGINF, m2 = NEGINF, m3 = NEGINF;
    float s0 = 0.f, s1 = 0.f, s2 = 0.f, s3 = 0.f;

    #pragma unroll 8
    for (int r = 0; r < RPB; r++) {
        float4 v = __ldg((const float4*)(x + base + (size_t)r * KK));
        if (v.x > m0) { s0 = s0 * __expf((m0 - v.x) * INV_EPS) + 1.0f; m0 = v.x; }
        else          { s0 += __expf((v.x - m0) * INV_EPS); }
        if (v.y > m1) { s1 = s1 * __expf((m1 - v.y) * INV_EPS) + 1.0f; m1 = v.y; }
        else          { s1 += __expf((v.y - m1) * INV_EPS); }
        if (v.z > m2) { s2 = s2 * __expf((m2 - v.z) * INV_EPS) + 1.0f; m2 = v.z; }
        else          { s2 += __expf((v.z - m2) * INV_EPS); }
        if (v.w > m3) { s3 = s3 * __expf((m3 - v.w) * INV_EPS) + 1.0f; m3 = v.w; }
        else          { s3 += __expf((v.w - m3) * INV_EPS); }
    }
    int c = blockIdx.y;
    *(float4*)&g_part_m[c][k0] = make_float4(m0, m1, m2, m3);
    *(float4*)&g_part_s[c][k0] = make_float4(s0, s1, s2, s3);

    float bm = fmaxf(fmaxf(m0, m1), fmaxf(m2, m3));
    #pragma unroll
    for (int o = 16; o; o >>= 1) bm = fmaxf(bm, __shfl_xor_sync(0xffffffffu, bm, o));
    __shared__ float red[8];
    if ((threadIdx.x & 31) == 0) red[threadIdx.x >> 5] = bm;
    __syncthreads();
    if (threadIdx.x == 0) {
        float t = red[0];
        #pragma unroll
        for (int i = 1; i < 8; i++) t = fmaxf(t, red[i]);
        atomicMax(&g_Mbits, enc_f(t));
    }
}

// ---- two-stage fixups (wide stage A, tiny stage B) ----

__global__ __launch_bounds__(NTHR) void k_fix1A() {
    const int   k = blockIdx.x * NTHR + threadIdx.x;
    const int   c0 = blockIdx.y * (CHUNKS / GRP);
    const float M = dec_f(g_Mbits);
    float s = 0.f;
    #pragma unroll
    for (int c = 0; c < CHUNKS / GRP; c++)
        s += g_part_s[c0 + c][k] * __expf((g_part_m[c0 + c][k] - M) * INV_EPS);
    g_p2[blockIdx.y][k] = s;
}

__global__ __launch_bounds__(NTHR) void k_fixfA() {
    const int k  = blockIdx.x * NTHR + threadIdx.x;
    const int b0 = blockIdx.y * (FBLK / GRP);
    float s = 0.f;
    #pragma unroll 8
    for (int b = 0; b < FBLK / GRP; b++)
        s += g_partp[b0 + b][k];
    g_p2[blockIdx.y][k] = s;
}

// Stage B: combine GRP partials. mode 0: a[k]=1/s ; mode 1: a[k]/=s
__global__ __launch_bounds__(NTHR) void k_fixB(int mode) {
    const int k = blockIdx.x * NTHR + threadIdx.x;
    float s = 0.f;
    #pragma unroll
    for (int g = 0; g < GRP; g++) s += g_p2[g][k];
    g_a[k] = (mode == 0) ? (1.0f / s) : (g_a[k] / s);
}

// Fused Sinkhorn iteration: one read of x computes BOTH
//   t[b] = sum_k a[k]*E[b,k]   (row sums -> d[b] = 1/t[b])
//   p[k] = sum_b d[b]*a[k]*E[b,k]
__global__ __launch_bounds__(WTHR, 3) void k_fused(const float* __restrict__ x) {
    __shared__ float slot[2][16];
    const float M   = dec_f(g_Mbits);
    const int   tid = threadIdx.x;

    float4 av0 = __ldg((const float4*)g_a + tid);
    float4 av1 = __ldg((const float4*)g_a + tid + WTHR);

    const int     r0 = blockIdx.x * FROWS;
    const float4* xp = (const float4*)(x + (size_t)r0 * KK) + tid;

    float4 xv0 = __ldg(xp);
    float4 xv1 = __ldg(xp + WTHR);

    float4 pc0 = make_float4(0.f, 0.f, 0.f, 0.f);
    float4 pc1 = make_float4(0.f, 0.f, 0.f, 0.f);

    for (int r = 0; r < FROWS; r++) {
        float4 w0, w1;
        w0.x = av0.x * __expf((xv0.x - M) * INV_EPS);
        w0.y = av0.y * __expf((xv0.y - M) * INV_EPS);
        w0.z = av0.z * __expf((xv0.z - M) * INV_EPS);
        w0.w = av0.w * __expf((xv0.w - M) * INV_EPS);
        w1.x = av1.x * __expf((xv1.x - M) * INV_EPS);
        w1.y = av1.y * __expf((xv1.y - M) * INV_EPS);
        w1.z = av1.z * __expf((xv1.z - M) * INV_EPS);
        w1.w = av1.w * __expf((xv1.w - M) * INV_EPS);
        float acc = ((w0.x + w0.y) + (w0.z + w0.w))
                  + ((w1.x + w1.y) + (w1.z + w1.w));
        // prefetch next row (xv regs free) before the reduction barrier
        if (r + 1 < FROWS) {
            xv0 = __ldg(xp + (size_t)(r + 1) * (KK / 4));
            xv1 = __ldg(xp + (size_t)(r + 1) * (KK / 4) + WTHR);
        }
        float t = rowReduce16(acc, slot, r & 1);
        float d = 1.0f / t;
        pc0.x += d * w0.x;  pc0.y += d * w0.y;
        pc0.z += d * w0.z;  pc0.w += d * w0.w;
        pc1.x += d * w1.x;  pc1.y += d * w1.y;
        pc1.z += d * w1.z;  pc1.w += d * w1.w;
    }
    float4* pp = (float4*)&g_partp[blockIdx.x][0];
    pp[tid]        = pc0;
    pp[tid + WTHR] = pc1;
}

// Final: out[b,k] = a3[k]*E[b,k] / sum_k a3[k]*E[b,k]
__global__ __launch_bounds__(WTHR, 3) void k_final(const float* __restrict__ x,
                                                   float* __restrict__ out) {
    __shared__ float slot[2][16];
    const float M   = dec_f(g_Mbits);
    const int   tid = threadIdx.x;

    float4 av0 = __ldg((const float4*)g_a + tid);
    float4 av1 = __ldg((const float4*)g_a + tid + WTHR);

    const int     r0 = blockIdx.x * OROWS;
    const float4* xp = (const float4*)(x + (size_t)r0 * KK) + tid;

    float4 xv0 = __ldg(xp);
    float4 xv1 = __ldg(xp + WTHR);

    for (int r = 0; r < OROWS; r++) {
        float4 w0, w1;
        w0.x = av0.x * __expf((xv0.x - M) * INV_EPS);
        w0.y = av0.y * __expf((xv0.y - M) * INV_EPS);
        w0.z = av0.z * __expf((xv0.z - M) * INV_EPS);
        w0.w = av0.w * __expf((xv0.w - M) * INV_EPS);
        w1.x = av1.x * __expf((xv1.x - M) * INV_EPS);
        w1.y = av1.y * __expf((xv1.y - M) * INV_EPS);
        w1.z = av1.z * __expf((xv1.z - M) * INV_EPS);
        w1.w = av1.w * __expf((xv1.w - M) * INV_EPS);
        float acc = ((w0.x + w0.y) + (w0.z + w0.w))
                  + ((w1.x + w1.y) + (w1.z + w1.w));
        if (r + 1 < OROWS) {
            xv0 = __ldg(xp + (size_t)(r + 1) * (KK / 4));
            xv1 = __ldg(xp + (size_t)(r + 1) * (KK / 4) + WTHR);
        }
        float t   = rowReduce16(acc, slot, r & 1);
        float inv = 1.0f / t;
        float4* po = (float4*)(out + (size_t)(r0 + r) * KK) + tid;
        po[0]    = make_float4(w0.x * inv, w0.y * inv, w0.z * inv, w0.w * inv);
        po[WTHR] = make_float4(w1.x * inv, w1.y * inv, w1.z * inv, w1.w * inv);
    }
}

extern "C" void kernel_launch(void* const* d_in, const int* in_sizes, int n_in,
                              void* d_out, int out_size) {
    const float* x   = (const float*)d_in[0];
    float*       out = (float*)d_out;

    dim3 cg(KK / CPB, CHUNKS);              // (4, 128)
    dim3 rg(KK / NTHR, GRP);                // (16, 16) stage-A grids
    k_pass1<<<cg, NTHR>>>(x);
    k_fix1A<<<rg, NTHR>>>();
    k_fixB<<<KK / NTHR, NTHR>>>(0);
    for (int i = 0; i < 2; i++) {           // two fused Sinkhorn iterations
        k_fused<<<FBLK, WTHR>>>(x);
        k_fixfA<<<rg, NTHR>>>();
        k_fixB<<<KK / NTHR, NTHR>>>(1);
    }
    k_final<<<BB / OROWS, WTHR>>>(x, out);
}

// round 6
// speedup vs baseline: 1.0213x; 1.0213x over previous
#include <cuda_runtime.h>

#define BB 16384
#define KK 4096
#define CHUNKS 128          // row-chunks for pass1
#define RPB (BB / CHUNKS)   // 128 rows per chunk
#define CPB 1024            // columns per pass1 block (256 thr * float4)
#define NTHR 256
#define FROWS 16            // rows per fused block
#define FBLK (BB / FROWS)   // 1024 fused blocks
#define OROWS 8             // rows per final block
#define GRP 16              // reduction groups for two-stage fixups
#define INV_EPS 20.0f       // 1/0.05

// ---- scratch (device globals; no allocation) ----
__device__ float    g_part_m[CHUNKS][KK];
__device__ float    g_part_s[CHUNKS][KK];
__device__ float    g_partp[FBLK][KK];   // fused col partials (16.8 MB)
__device__ float    g_p2[GRP][KK];       // stage-A partials
__device__ float    g_a[KK];             // a[k]
__device__ unsigned g_Mbits;             // 0-init at load; atomicMax idempotent

__device__ __forceinline__ unsigned enc_f(float x) {
    unsigned u = __float_as_uint(x);
    return (u & 0x80000000u) ? ~u : (u | 0x80000000u);
}
__device__ __forceinline__ float dec_f(unsigned u) {
    return (u & 0x80000000u) ? __uint_as_float(u & 0x7FFFFFFFu)
                             : __uint_as_float(~u);
}

// Single-barrier 8-warp row-sum, double-buffered by parity. Deterministic:
// fixed shuffle tree + fixed 8-slot fold identical in every thread.
__device__ __forceinline__ float rowReduce(float v, float (*slot)[8], int par) {
    #pragma unroll
    for (int o = 16; o; o >>= 1) v += __shfl_xor_sync(0xffffffffu, v, o);
    if ((threadIdx.x & 31) == 0) slot[par][threadIdx.x >> 5] = v;
    __syncthreads();
    float t = ((slot[par][0] + slot[par][1]) + (slot[par][2] + slot[par][3]))
            + ((slot[par][4] + slot[par][5]) + (slot[par][6] + slot[par][7]));
    return t;
}

// Pass 1: per-chunk online column (over b) sums of exp with local max,
// plus global max via atomicMax.
__global__ __launch_bounds__(NTHR) void k_pass1(const float* __restrict__ x) {
    const int    k0   = blockIdx.x * CPB + threadIdx.x * 4;
    const size_t base = (size_t)blockIdx.y * RPB * KK + k0;
    const float  NEGINF = __int_as_float(0xff800000);
    float m0 = NEGINF, m1 = NEGINF, m2 = NEGINF, m3 = NEGINF;
    float s0 = 0.f, s1 = 0.f, s2 = 0.f, s3 = 0.f;

    #pragma unroll 8
    for (int r = 0; r < RPB; r++) {
        float4 v = __ldg((const float4*)(x + base + (size_t)r * KK));
        if (v.x > m0) { s0 = s0 * __expf((m0 - v.x) * INV_EPS) + 1.0f; m0 = v.x; }
        else          { s0 += __expf((v.x - m0) * INV_EPS); }
        if (v.y > m1) { s1 = s1 * __expf((m1 - v.y) * INV_EPS) + 1.0f; m1 = v.y; }
        else          { s1 += __expf((v.y - m1) * INV_EPS); }
        if (v.z > m2) { s2 = s2 * __expf((m2 - v.z) * INV_EPS) + 1.0f; m2 = v.z; }
        else          { s2 += __expf((v.z - m2) * INV_EPS); }
        if (v.w > m3) { s3 = s3 * __expf((m3 - v.w) * INV_EPS) + 1.0f; m3 = v.w; }
        else          { s3 += __expf((v.w - m3) * INV_EPS); }
    }
    int c = blockIdx.y;
    *(float4*)&g_part_m[c][k0] = make_float4(m0, m1, m2, m3);
    *(float4*)&g_part_s[c][k0] = make_float4(s0, s1, s2, s3);

    float bm = fmaxf(fmaxf(m0, m1), fmaxf(m2, m3));
    #pragma unroll
    for (int o = 16; o; o >>= 1) bm = fmaxf(bm, __shfl_xor_sync(0xffffffffu, bm, o));
    __shared__ float red[8];
    if ((threadIdx.x & 31) == 0) red[threadIdx.x >> 5] = bm;
    __syncthreads();
    if (threadIdx.x == 0) {
        float t = red[0];
        #pragma unroll
        for (int i = 1; i < 8; i++) t = fmaxf(t, red[i]);
        atomicMax(&g_Mbits, enc_f(t));
    }
}

// ---- two-stage fixups (wide stage A, tiny stage B) ----

__global__ __launch_bounds__(NTHR) void k_fix1A() {
    const int   k = blockIdx.x * NTHR + threadIdx.x;
    const int   c0 = blockIdx.y * (CHUNKS / GRP);
    const float M = dec_f(g_Mbits);
    float s = 0.f;
    #pragma unroll
    for (int c = 0; c < CHUNKS / GRP; c++)
        s += g_part_s[c0 + c][k] * __expf((g_part_m[c0 + c][k] - M) * INV_EPS);
    g_p2[blockIdx.y][k] = s;
}

__global__ __launch_bounds__(NTHR) void k_fixfA() {
    const int k  = blockIdx.x * NTHR + threadIdx.x;
    const int b0 = blockIdx.y * (FBLK / GRP);
    float s = 0.f;
    #pragma unroll 8
    for (int b = 0; b < FBLK / GRP; b++)
        s += g_partp[b0 + b][k];
    g_p2[blockIdx.y][k] = s;
}

// Stage B: combine GRP partials. mode 0: a[k]=1/s ; mode 1: a[k]/=s
__global__ __launch_bounds__(NTHR) void k_fixB(int mode) {
    const int k = blockIdx.x * NTHR + threadIdx.x;
    float s = 0.f;
    #pragma unroll
    for (int g = 0; g < GRP; g++) s += g_p2[g][k];
    g_a[k] = (mode == 0) ? (1.0f / s) : (g_a[k] / s);
}

// Fused Sinkhorn iteration: one read of x computes BOTH
//   t[b] = sum_k a[k]*E[b,k]   (row sums -> d[b] = 1/t[b])
//   p[k] = sum_b d[b]*a[k]*E[b,k]
// Triple-buffered: row r+2 loads issued BEFORE row r's barrier
// (~1.7 row-periods of latency tolerance).
__global__ __launch_bounds__(NTHR, 3) void k_fused(const float* __restrict__ x) {
    __shared__ float slot[2][8];
    __shared__ __align__(16) float sa[KK];
    const float M = dec_f(g_Mbits);
    #pragma unroll
    for (int j = 0; j < 4; j++)
        ((float4*)sa)[threadIdx.x + j * NTHR] =
            __ldg((const float4*)g_a + threadIdx.x + j * NTHR);
    __syncthreads();
    const float4* sa4 = (const float4*)sa;

    const int     r0 = blockIdx.x * FROWS;
    const float4* xp = (const float4*)(x + (size_t)r0 * KK) + threadIdx.x;

    float4 buf[3][4];
    #pragma unroll
    for (int j = 0; j < 4; j++) {
        buf[0][j] = __ldg(xp + j * NTHR);
        buf[1][j] = __ldg(xp + (KK / 4) + j * NTHR);
    }

    float4 pc[4];
    #pragma unroll
    for (int j = 0; j < 4; j++) pc[j] = make_float4(0.f, 0.f, 0.f, 0.f);

    #pragma unroll
    for (int r = 0; r < FROWS; r++) {
        const int cur = r % 3;
        const int pre = (r + 2) % 3;
        float acc = 0.f;
        #pragma unroll
        for (int j = 0; j < 4; j++) {          // w computed IN PLACE over buf[cur]
            float4 a = sa4[threadIdx.x + j * NTHR];
            buf[cur][j].x = a.x * __expf((buf[cur][j].x - M) * INV_EPS);
            buf[cur][j].y = a.y * __expf((buf[cur][j].y - M) * INV_EPS);
            buf[cur][j].z = a.z * __expf((buf[cur][j].z - M) * INV_EPS);
            buf[cur][j].w = a.w * __expf((buf[cur][j].w - M) * INV_EPS);
            acc += (buf[cur][j].x + buf[cur][j].y)
                 + (buf[cur][j].z + buf[cur][j].w);
        }
        if (r + 2 < FROWS) {                   // prefetch BEFORE the barrier
            #pragma unroll
            for (int j = 0; j < 4; j++)
                buf[pre][j] = __ldg(xp + (size_t)(r + 2) * (KK / 4) + j * NTHR);
        }
        float t = rowReduce(acc, slot, r & 1);
        float d = 1.0f / t;
        #pragma unroll
        for (int j = 0; j < 4; j++) {
            pc[j].x += d * buf[cur][j].x;
            pc[j].y += d * buf[cur][j].y;
            pc[j].z += d * buf[cur][j].z;
            pc[j].w += d * buf[cur][j].w;
        }
    }
    float4* pp = (float4*)&g_partp[blockIdx.x][0];
    #pragma unroll
    for (int j = 0; j < 4; j++) pp[threadIdx.x + j * NTHR] = pc[j];
}

// Final: out[b,k] = a3[k]*E[b,k] / sum_k a3[k]*E[b,k]  (same triple-buffering)
__global__ __launch_bounds__(NTHR, 3) void k_final(const float* __restrict__ x,
                                                   float* __restrict__ out) {
    __shared__ float slot[2][8];
    __shared__ __align__(16) float sa[KK];
    const float M = dec_f(g_Mbits);
    #pragma unroll
    for (int j = 0; j < 4; j++)
        ((float4*)sa)[threadIdx.x + j * NTHR] =
            __ldg((const float4*)g_a + threadIdx.x + j * NTHR);
    __syncthreads();
    const float4* sa4 = (const float4*)sa;

    const int     r0 = blockIdx.x * OROWS;
    const float4* xp = (const float4*)(x + (size_t)r0 * KK) + threadIdx.x;

    float4 buf[3][4];
    #pragma unroll
    for (int j = 0; j < 4; j++) {
        buf[0][j] = __ldg(xp + j * NTHR);
        buf[1][j] = __ldg(xp + (KK / 4) + j * NTHR);
    }

    #pragma unroll
    for (int r = 0; r < OROWS; r++) {
        const int cur = r % 3;
        const int pre = (r + 2) % 3;
        float acc = 0.f;
        #pragma unroll
        for (int j = 0; j < 4; j++) {
            float4 a = sa4[threadIdx.x + j * NTHR];
            buf[cur][j].x = a.x * __expf((buf[cur][j].x - M) * INV_EPS);
            buf[cur][j].y = a.y * __expf((buf[cur][j].y - M) * INV_EPS);
            buf[cur][j].z = a.z * __expf((buf[cur][j].z - M) * INV_EPS);
            buf[cur][j].w = a.w * __expf((buf[cur][j].w - M) * INV_EPS);
            acc += (buf[cur][j].x + buf[cur][j].y)
                 + (buf[cur][j].z + buf[cur][j].w);
        }
        if (r + 2 < OROWS) {
            #pragma unroll
            for (int j = 0; j < 4; j++)
                buf[pre][j] = __ldg(xp + (size_t)(r + 2) * (KK / 4) + j * NTHR);
        }
        float t   = rowReduce(acc, slot, r & 1);
        float inv = 1.0f / t;
        float4* po = (float4*)(out + (size_t)(r0 + r) * KK) + threadIdx.x;
        #pragma unroll
        for (int j = 0; j < 4; j++)
            po[j * NTHR] = make_float4(buf[cur][j].x * inv, buf[cur][j].y * inv,
                                       buf[cur][j].z * inv, buf[cur][j].w * inv);
    }
}

extern "C" void kernel_launch(void* const* d_in, const int* in_sizes, int n_in,
                              void* d_out, int out_size) {
    const float* x   = (const float*)d_in[0];
    float*       out = (float*)d_out;

    dim3 cg(KK / CPB, CHUNKS);              // (4, 128)
    dim3 rg(KK / NTHR, GRP);                // (16, 16) stage-A grids
    k_pass1<<<cg, NTHR>>>(x);
    k_fix1A<<<rg, NTHR>>>();
    k_fixB<<<KK / NTHR, NTHR>>>(0);
    for (int i = 0; i < 2; i++) {           // two fused Sinkhorn iterations
        k_fused<<<FBLK, NTHR>>>(x);
        k_fixfA<<<rg, NTHR>>>();
        k_fixB<<<KK / NTHR, NTHR>>>(1);
    }
    k_final<<<BB / OROWS, NTHR>>>(x, out);
}